// round 15
// baseline (speedup 1.0000x reference)
#include <cuda_runtime.h>
#include <cuda_fp16.h>
#include <cstdint>
#include <math.h>

#define BATCH 32
#define LSEQ  256
#define DMODEL 384
#define DIN   768
#define NST   16
#define RLOW  48
#define NLAYER 4
#define NCLS  1000
#define MROWS (BATCH*LSEQ)      // 8192
#define KPATCH 588              // 3*14*14
#define KPAD   592              // padded for 16B-aligned rows
#define PROJW 80                // R + 2*NST

// ---- weight split buffer layout (halves) ----
#define SZ_PW  (DMODEL*KPAD)
#define OFF_IN (SZ_PW)
#define SZ_IN  (2*DIN*DMODEL)
#define OFF_XP (OFF_IN + 4*SZ_IN)
#define SZ_XP  (PROJW*DIN)
#define OFF_DT (OFF_XP + 4*SZ_XP)
#define SZ_DT  (DIN*RLOW)
#define OFF_OW (OFF_DT + 4*SZ_DT)
#define SZ_OW  (DMODEL*DIN)
#define TOTW   (OFF_OW + 4*SZ_OW)

// ---------------- scratch (device globals; no allocation allowed) ----------
__device__ float g_t   [MROWS*DMODEL];
__device__ float g_xn  [MROWS*DMODEL];
__device__ float g_xz  [MROWS*2*DIN];
__device__ float g_xb  [MROWS*DIN];
__device__ float g_proj[MROWS*PROJW];
__device__ float g_dt  [MROWS*DIN];
__device__ float g_part[4*MROWS*DMODEL];   // split-K partials

__device__ __half g_wh  [TOTW];
__device__ __half g_wl  [TOTW];
__device__ __half g_imh [MROWS*KPAD + 64];
__device__ __half g_iml [MROWS*KPAD + 64];
__device__ __half g_xnh [MROWS*DMODEL];
__device__ __half g_xnl [MROWS*DMODEL];
__device__ __half g_xbh [MROWS*DIN];
__device__ __half g_xbl [MROWS*DIN];
__device__ __half g_prh [MROWS*PROJW];
__device__ __half g_prl [MROWS*PROJW];
__device__ __half g_yh  [MROWS*DIN];
__device__ __half g_yl  [MROWS*DIN];

__device__ __forceinline__ float softplus_f(float v){
    return fmaxf(v, 0.f) + log1pf(expf(-fabsf(v)));
}
__device__ __forceinline__ float silu_f(float v){
    return v / (1.f + __expf(-v));
}
__device__ __forceinline__ void split_f(float v, __half& h, __half& l){
    h = __float2half_rn(v);
    l = __float2half_rn(v - __half2float(h));
}

__device__ __forceinline__ void mma16(float* c, const uint32_t* a, const uint32_t* b){
    asm volatile("mma.sync.aligned.m16n8k16.row.col.f32.f16.f16.f32 "
        "{%0,%1,%2,%3}, {%4,%5,%6,%7}, {%8,%9}, {%0,%1,%2,%3};"
        : "+f"(c[0]), "+f"(c[1]), "+f"(c[2]), "+f"(c[3])
        : "r"(a[0]), "r"(a[1]), "r"(a[2]), "r"(a[3]), "r"(b[0]), "r"(b[1]));
}
__device__ __forceinline__ void ldsm_x4(uint32_t* r, uint32_t addr){
    asm volatile("ldmatrix.sync.aligned.m8n8.x4.shared.b16 {%0,%1,%2,%3}, [%4];"
        : "=r"(r[0]), "=r"(r[1]), "=r"(r[2]), "=r"(r[3]) : "r"(addr));
}
__device__ __forceinline__ uint32_t smem_u32(const void* p){
    uint32_t a;
    asm("{ .reg .u64 t; cvta.to.shared.u64 t, %1; cvt.u32.u64 %0, t; }" : "=r"(a) : "l"(p));
    return a;
}
__device__ __forceinline__ void cp_async16(uint32_t dst, const void* src, int bytes){
    asm volatile("cp.async.ca.shared.global [%0], [%1], 16, %2;"
        :: "r"(dst), "l"(src), "r"(bytes) : "memory");
}
#define CP_COMMIT() asm volatile("cp.async.commit_group;" ::: "memory")
#define CP_WAIT0()  asm volatile("cp.async.wait_group 0;"  ::: "memory")

// ---------------- weight split: fp32 -> (hi, lo) fp16 ----------------------
__global__ void split_weights(const float* __restrict__ pw,
                              const float* __restrict__ inw,
                              const float* __restrict__ xpw,
                              const float* __restrict__ dtw,
                              const float* __restrict__ ow,
                              __half* __restrict__ wh, __half* __restrict__ wl)
{
    int i = blockIdx.x*blockDim.x + threadIdx.x;
    if (i >= TOTW) return;
    float v;
    if (i < OFF_IN){
        int row = i / KPAD, col = i - row*KPAD;
        v = (col < KPATCH) ? pw[row*KPATCH + col] : 0.f;
    }
    else if (i < OFF_XP) v = inw[i-OFF_IN];
    else if (i < OFF_DT) v = xpw[i-OFF_XP];
    else if (i < OFF_OW) v = dtw[i-OFF_DT];
    else                 v = ow [i-OFF_OW];
    __half h, l; split_f(v, h, l);
    wh[i] = h; wl[i] = l;
}

// ---------------- im2col gather + split (patch embed A operand) ------------
__global__ void im2col_split(const float* __restrict__ X,
                             __half* __restrict__ oh, __half* __restrict__ ol)
{
    int idx = blockIdx.x*blockDim.x + threadIdx.x;
    if (idx >= MROWS*KPAD) return;
    int m = idx / KPAD, k = idx - m*KPAD;
    float v = 0.f;
    if (k < KPATCH){
        int b = m >> 8, l = m & 255;
        int py = l >> 4, px = l & 15;
        int cc = k / 196, rem = k - cc*196;
        int ky = rem / 14, kx = rem - ky*14;
        v = X[((size_t)(b*3 + cc)*224 + (py*14+ky))*224 + (px*14+kx)];
    }
    __half h, l2; split_f(v, h, l2);
    oh[idx] = h; ol[idx] = l2;
}

// =================== fp16-split GEMM, cp.async + ldmatrix ===================
#define KCH   32
#define HSTR  40
#define SUBT  (128*HSTR)
#define STAGE_H (4*SUBT)
#define SMEM_G  (2*STAGE_H*2)

// MODE 0: plain  1: += res  2: + bias[n]  3: softplus(. + bias[n])
// MODE 4: split-K partial
template<int MODE, int SPLIT, int NPROD>
__global__ void __launch_bounds__(256,2) mma_gemm(
        const __half* __restrict__ Ah_g, const __half* __restrict__ Al_g, int lda,
        const __half* __restrict__ Bh_g, const __half* __restrict__ Bl_g, int Nrows,
        float* __restrict__ C, int ldc, int Kd,
        const float* __restrict__ aux,
        __half* __restrict__ Ch, __half* __restrict__ Cl,
        int cpz)
{
    extern __shared__ __half smem[];
    const uint32_t sb = smem_u32(smem);
    const int tid = threadIdx.x;
    const int wid = tid >> 5, lane = tid & 31;
    const int wm = wid & 1, wn = wid >> 1;
    const int g = lane >> 2, t = lane & 3;
    const int bm = blockIdx.y << 7, bn = blockIdx.x << 7;
    const int NC = (Kd + KCH - 1) / KCH;

    int cbeg = 0, cend = NC;
    if (MODE == 4){
        cbeg = blockIdx.z * cpz;
        cend = min(NC, cbeg + cpz);
        C += (size_t)blockIdx.z * MROWS * ldc;
    }

    const int ldrow = (lane & 7) + ((lane >> 3) & 1)*8;
    const int ldk   = (lane >> 4)*8;
    const uint32_t offA = (uint32_t)(((wm*64 + ldrow)*HSTR + ldk)*2);
    const uint32_t offB = (uint32_t)(((wn*32 + ldrow)*HSTR + ldk)*2 + 2*SUBT*2);

    float acc[4][4][4];
    #pragma unroll
    for (int i=0;i<4;i++)
        #pragma unroll
        for (int j=0;j<4;j++)
            #pragma unroll
            for (int q=0;q<4;q++) acc[i][j][q]=0.f;

    constexpr int NVEC = (NPROD == 3) ? 8 : 6;
    auto issue = [&](int j){
        const int k0 = j*KCH;
        const uint32_t stage = sb + (uint32_t)((j&1)*STAGE_H)*2u;
        #pragma unroll
        for (int i=0;i<NVEC;i++){
            int e    = tid + (i<<8);
            int subi = e >> 9;
            int sub  = (NPROD == 3) ? subi : (subi == 0 ? 0 : subi + 1); // {Ah,Bh,Bl}
            int r    = (e & 511) >> 2;
            int c8   = e & 3;
            int gk   = k0 + (c8<<3);
            int bytes = (Kd - gk)*2;
            bytes = bytes < 0 ? 0 : (bytes > 16 ? 16 : bytes);
            const __half* src;
            if (sub < 2){
                src = (sub ? Al_g : Ah_g) + (size_t)(bm + r)*lda + gk;
            } else {
                int gr = bn + r;
                if (gr >= Nrows) bytes = 0;
                src = (sub == 3 ? Bl_g : Bh_g);
                if (bytes) src += (size_t)gr*Kd + gk;
            }
            uint32_t dst = stage + (uint32_t)(sub*SUBT + r*HSTR + (c8<<3))*2u;
            cp_async16(dst, src, bytes);
        }
        CP_COMMIT();
    };

    issue(cbeg);

    for (int j=cbeg;j<cend;j++){
        CP_WAIT0();
        __syncthreads();
        if (j+1 < cend) issue(j+1);

        const uint32_t stage = sb + (uint32_t)((j&1)*STAGE_H)*2u;
        const uint32_t aBase = stage + offA;
        const uint32_t bBase = stage + offB;

        #pragma unroll
        for (int ks=0; ks<2; ks++){
            const uint32_t kof = (uint32_t)(ks*16*2);
            uint32_t ah[4][4], al[4][4];
            #pragma unroll
            for (int im=0; im<4; im++){
                uint32_t a = aBase + (uint32_t)(im*16*HSTR*2) + kof;
                ldsm_x4(ah[im], a);
                if (NPROD == 3) ldsm_x4(al[im], a + (uint32_t)(SUBT*2));
            }
            uint32_t bh[4][2], bl[4][2];
            #pragma unroll
            for (int p=0; p<2; p++){
                uint32_t b = bBase + (uint32_t)(p*16*HSTR*2) + kof;
                uint32_t r[4];
                ldsm_x4(r, b);
                bh[2*p][0]=r[0]; bh[2*p+1][0]=r[1]; bh[2*p][1]=r[2]; bh[2*p+1][1]=r[3];
                ldsm_x4(r, b + (uint32_t)(SUBT*2));
                bl[2*p][0]=r[0]; bl[2*p+1][0]=r[1]; bl[2*p][1]=r[2]; bl[2*p+1][1]=r[3];
            }
            #pragma unroll
            for (int im=0; im<4; im++)
                #pragma unroll
                for (int in_=0; in_<4; in_++)
                    mma16(acc[im][in_], ah[im], bh[in_]);
            #pragma unroll
            for (int im=0; im<4; im++)
                #pragma unroll
                for (int in_=0; in_<4; in_++)
                    mma16(acc[im][in_], ah[im], bl[in_]);
            if (NPROD == 3){
                #pragma unroll
                for (int im=0; im<4; im++)
                    #pragma unroll
                    for (int in_=0; in_<4; in_++)
                        mma16(acc[im][in_], al[im], bh[in_]);
            }
        }
    }

    #pragma unroll
    for (int im=0; im<4; im++){
        int r0 = bm + wm*64 + im*16 + g;
        #pragma unroll
        for (int in_=0; in_<4; in_++){
            int cc = bn + wn*32 + in_*8 + (t<<1);
            if (cc < Nrows){
                float2 v0 = make_float2(acc[im][in_][0], acc[im][in_][1]);
                float2 v1 = make_float2(acc[im][in_][2], acc[im][in_][3]);
                if (MODE==1){
                    float2 r = *(const float2*)&aux[(size_t)r0*ldc + cc];
                    v0.x += r.x; v0.y += r.y;
                    float2 s = *(const float2*)&aux[(size_t)(r0+8)*ldc + cc];
                    v1.x += s.x; v1.y += s.y;
                } else if (MODE==2 || MODE==3){
                    float2 b = *(const float2*)&aux[cc];
                    v0.x += b.x; v0.y += b.y;
                    v1.x += b.x; v1.y += b.y;
                    if (MODE==3){
                        v0.x = softplus_f(v0.x); v0.y = softplus_f(v0.y);
                        v1.x = softplus_f(v1.x); v1.y = softplus_f(v1.y);
                    }
                }
                *(float2*)&C[(size_t)r0*ldc + cc]     = v0;
                *(float2*)&C[(size_t)(r0+8)*ldc + cc] = v1;
                if (SPLIT){
                    __half h0,l0,h1,l1;
                    split_f(v0.x, h0, l0); split_f(v0.y, h1, l1);
                    *(__half2*)&Ch[(size_t)r0*ldc + cc] = __halves2half2(h0,h1);
                    *(__half2*)&Cl[(size_t)r0*ldc + cc] = __halves2half2(l0,l1);
                    split_f(v1.x, h0, l0); split_f(v1.y, h1, l1);
                    *(__half2*)&Ch[(size_t)(r0+8)*ldc + cc] = __halves2half2(h0,h1);
                    *(__half2*)&Cl[(size_t)(r0+8)*ldc + cc] = __halves2half2(l0,l1);
                }
            }
        }
    }
}

// ---------------- split-K reduce (x_proj only) -------------------------------
__global__ void reduce4_split(const float* __restrict__ P,
                              float* __restrict__ proj,
                              __half* __restrict__ ph, __half* __restrict__ pl)
{
    int i = blockIdx.x*blockDim.x + threadIdx.x;
    if (i >= MROWS*PROJW) return;
    const int N = MROWS*PROJW;
    float s = (P[i] + P[N + i]) + (P[2*N + i] + P[3*N + i]);
    proj[i] = s;
    __half h, l; split_f(s, h, l);
    ph[i] = h; pl[i] = l;
}

// ------- fused LN kernels: consume split-K partials, produce t & splits -----
// MODE_T 0: t_new = P0 + P1 + bias[c]   (patch output)
//        1: t_new = t + P0 + P1         (residual accumulate)
template<int MODE_T>
__global__ void ln_split_fused(const float* __restrict__ P,
                               const float* __restrict__ bias,
                               float* __restrict__ tbuf,
                               const float* __restrict__ w,
                               const float* __restrict__ b,
                               __half* __restrict__ oh, __half* __restrict__ ol)
{
    int row  = blockIdx.x*8 + (threadIdx.x >> 5);
    int lane = threadIdx.x & 31;
    const size_t rb = (size_t)row*DMODEL;
    float v[12]; float s=0.f, sq=0.f;
    #pragma unroll
    for (int i=0;i<12;i++){
        int c = lane + i*32;
        float tn = P[rb + c] + P[(size_t)MROWS*DMODEL + rb + c];
        if (MODE_T == 0) tn += bias[c];
        else             tn += tbuf[rb + c];
        tbuf[rb + c] = tn;
        v[i] = tn; s += tn; sq += tn*tn;
    }
    #pragma unroll
    for (int o=16;o;o>>=1){
        s  += __shfl_xor_sync(0xffffffffu, s,  o);
        sq += __shfl_xor_sync(0xffffffffu, sq, o);
    }
    float m   = s  * (1.f/DMODEL);
    float var = sq * (1.f/DMODEL) - m*m;
    float r   = rsqrtf(var + 1e-5f);
    #pragma unroll
    for (int i=0;i<12;i++){
        int c = lane + i*32;
        float o = (v[i]-m)*r*w[c] + b[c];
        __half h, l; split_f(o, h, l);
        oh[rb + c] = h;
        ol[rb + c] = l;
    }
}

// final LN fused with residual reduce: xn = LN(t + P0 + P1)
__global__ void layernorm_fused(const float* __restrict__ P,
                                const float* __restrict__ tbuf,
                                const float* __restrict__ w,
                                const float* __restrict__ b,
                                float* __restrict__ out)
{
    int row  = blockIdx.x*8 + (threadIdx.x >> 5);
    int lane = threadIdx.x & 31;
    const size_t rb = (size_t)row*DMODEL;
    float v[12]; float s=0.f, sq=0.f;
    #pragma unroll
    for (int i=0;i<12;i++){
        int c = lane + i*32;
        float tn = tbuf[rb + c] + P[rb + c] + P[(size_t)MROWS*DMODEL + rb + c];
        v[i] = tn; s += tn; sq += tn*tn;
    }
    #pragma unroll
    for (int o=16;o;o>>=1){
        s  += __shfl_xor_sync(0xffffffffu, s,  o);
        sq += __shfl_xor_sync(0xffffffffu, sq, o);
    }
    float m   = s  * (1.f/DMODEL);
    float var = sq * (1.f/DMODEL) - m*m;
    float r   = rsqrtf(var + 1e-5f);
    #pragma unroll
    for (int i=0;i<12;i++){
        int c = lane + i*32;
        out[rb + c] = (v[i]-m)*r*w[c] + b[c];
    }
}

// ---------------- causal depthwise conv1d + bias + silu, split out ---------
__global__ void conv_silu_k(const float* __restrict__ xz,
                            const float* __restrict__ cw,
                            const float* __restrict__ cb,
                            float* __restrict__ xb,
                            __half* __restrict__ xbh, __half* __restrict__ xbl)
{
    int idx = blockIdx.x*blockDim.x + threadIdx.x;
    if (idx >= MROWS*DIN) return;
    int d  = idx % DIN;
    int bl_ = idx / DIN;
    int l  = bl_ & 255;
    int b  = bl_ >> 8;
    float acc = cb[d];
    #pragma unroll
    for (int j=0;j<4;j++){
        int ls = l - 3 + j;
        if (ls >= 0)
            acc = fmaf(xz[(size_t)(b*LSEQ+ls)*(2*DIN) + d], cw[d*4+j], acc);
    }
    float o = silu_f(acc);
    xb[idx] = o;
    __half h, lo; split_f(o, h, lo);
    xbh[idx] = h; xbl[idx] = lo;
}

// ---------------- selective scan: thread per (b,d, n-quad) ------------------
__global__ void __launch_bounds__(256) scan_k(
                       const float* __restrict__ dtp,
                       const float* __restrict__ xbp,
                       const float* __restrict__ proj,
                       const float* __restrict__ xz,
                       const float* __restrict__ A_log,
                       const float* __restrict__ Dp,
                       __half* __restrict__ yh, __half* __restrict__ yl)
{
    const int tid = threadIdx.x;
    const int nq  = tid & 3;
    const int dl  = tid >> 2;
    const int d   = blockIdx.x*64 + dl;
    const int b   = blockIdx.y;

    float A[4];
    bool okf = true;
    #pragma unroll
    for (int j=0;j<4;j++){
        int n = nq*4 + j;
        A[j] = -__expf(A_log[d*NST + n]);
        float kf = (float)(n+1);
        okf = okf && (fabsf(-A[j] - kf) <= 1e-5f*kf);
    }
    const bool fast = __all_sync(0xffffffffu, okf);
    const float Dd = Dp[d];
    float h0=0.f, h1=0.f, h2=0.f, h3=0.f;
    const size_t base = (size_t)b*LSEQ;

    size_t row = base;
    float dt_c = dtp[row*DIN + d];
    float xv_c = xbp[row*DIN + d];
    float4 B_c = *(const float4*)&proj[row*PROJW + RLOW + nq*4];
    float4 C_c = *(const float4*)&proj[row*PROJW + RLOW + NST + nq*4];

    for (int l=0; l<LSEQ; l++){
        row = base + l;
        float dt = dt_c, xv = xv_c;
        float4 Bv = B_c, Cv = C_c;
        if (l+1 < LSEQ){
            size_t r2 = row + 1;
            dt_c = dtp[r2*DIN + d];
            xv_c = xbp[r2*DIN + d];
            B_c  = *(const float4*)&proj[r2*PROJW + RLOW + nq*4];
            C_c  = *(const float4*)&proj[r2*PROJW + RLOW + NST + nq*4];
        }
        float dtx = dt*xv;
        if (fast){
            float e1 = __expf(-dt);
            float e2 = e1*e1;
            float e4 = e2*e2;
            float e8 = e4*e4;
            float bp = 1.f;
            if (nq & 1) bp = e4;
            if (nq & 2) bp *= e8;
            float r = bp*e1;
            h0 = fmaf(h0, r, dtx*Bv.x); r *= e1;
            h1 = fmaf(h1, r, dtx*Bv.y); r *= e1;
            h2 = fmaf(h2, r, dtx*Bv.z); r *= e1;
            h3 = fmaf(h3, r, dtx*Bv.w);
        } else {
            h0 = fmaf(h0, __expf(dt*A[0]), dtx*Bv.x);
            h1 = fmaf(h1, __expf(dt*A[1]), dtx*Bv.y);
            h2 = fmaf(h2, __expf(dt*A[2]), dtx*Bv.z);
            h3 = fmaf(h3, __expf(dt*A[3]), dtx*Bv.w);
        }
        float p = h0*Cv.x + h1*Cv.y + h2*Cv.z + h3*Cv.w;
        p += __shfl_xor_sync(0xffffffffu, p, 1);
        p += __shfl_xor_sync(0xffffffffu, p, 2);
        if (nq == 0){
            float z = xz[row*(2*DIN) + DIN + d];
            float yv = (p + xv*Dd) * silu_f(z);
            __half hh, ll; split_f(yv, hh, ll);
            yh[row*DIN + d] = hh;
            yl[row*DIN + d] = ll;
        }
    }
}

// ---------------- fused mean-pool + classifier -------------------------------
// block per batch image: pool xn over L into smem, then 384 threads cover the
// 1000 class dots from smem.
__global__ void __launch_bounds__(384) pool_cls_k(
        const float* __restrict__ ln,
        const float* __restrict__ w,
        const float* __restrict__ bias,
        float* __restrict__ out)
{
    __shared__ float sp[DMODEL];
    int b = blockIdx.x;
    int d = threadIdx.x;      // 384
    float s = 0.f;
    const float* base = ln + (size_t)b*LSEQ*DMODEL + d;
    #pragma unroll 4
    for (int l=0;l<LSEQ;l++)
        s += base[(size_t)l*DMODEL];
    sp[d] = s * (1.f/LSEQ);
    __syncthreads();

    for (int n = threadIdx.x; n < NCLS; n += 384){
        const float* wr = w + (size_t)n*DMODEL;
        float acc = bias[n];
        #pragma unroll 4
        for (int k=0;k<DMODEL;k++)
            acc = fmaf(sp[k], wr[k], acc);
        out[b*NCLS + n] = acc;
    }
}

// ---------------- launch -----------------------------------------------------
extern "C" void kernel_launch(void* const* d_in, const int* in_sizes, int n_in,
                              void* d_out, int out_size)
{
    const float* x         = (const float*)d_in[0];
    const float* patch_w   = (const float*)d_in[1];
    const float* patch_b   = (const float*)d_in[2];
    const float* norm_w    = (const float*)d_in[3];
    const float* norm_b    = (const float*)d_in[4];
    const float* in_proj_w = (const float*)d_in[5];
    const float* conv_w    = (const float*)d_in[6];
    const float* conv_b    = (const float*)d_in[7];
    const float* A_log     = (const float*)d_in[8];
    const float* D_ssm     = (const float*)d_in[9];
    const float* xproj_w   = (const float*)d_in[10];
    const float* dtproj_w  = (const float*)d_in[11];
    const float* dtproj_b  = (const float*)d_in[12];
    const float* out_proj_w= (const float*)d_in[13];
    const float* fnorm_w   = (const float*)d_in[14];
    const float* fnorm_b   = (const float*)d_in[15];
    const float* cls_w     = (const float*)d_in[16];
    const float* cls_b     = (const float*)d_in[17];
    float* out = (float*)d_out;

    float *t, *xn, *xz, *xb, *proj, *dt, *part;
    __half *wh, *wl, *imh, *iml, *xnh, *xnl, *xbh, *xbl, *prh, *prl, *yh, *yl;
    cudaGetSymbolAddress((void**)&t,    g_t);
    cudaGetSymbolAddress((void**)&xn,   g_xn);
    cudaGetSymbolAddress((void**)&xz,   g_xz);
    cudaGetSymbolAddress((void**)&xb,   g_xb);
    cudaGetSymbolAddress((void**)&proj, g_proj);
    cudaGetSymbolAddress((void**)&dt,   g_dt);
    cudaGetSymbolAddress((void**)&part, g_part);
    cudaGetSymbolAddress((void**)&wh,   g_wh);
    cudaGetSymbolAddress((void**)&wl,   g_wl);
    cudaGetSymbolAddress((void**)&imh,  g_imh);
    cudaGetSymbolAddress((void**)&iml,  g_iml);
    cudaGetSymbolAddress((void**)&xnh,  g_xnh);
    cudaGetSymbolAddress((void**)&xnl,  g_xnl);
    cudaGetSymbolAddress((void**)&xbh,  g_xbh);
    cudaGetSymbolAddress((void**)&xbl,  g_xbl);
    cudaGetSymbolAddress((void**)&prh,  g_prh);
    cudaGetSymbolAddress((void**)&prl,  g_prl);
    cudaGetSymbolAddress((void**)&yh,   g_yh);
    cudaGetSymbolAddress((void**)&yl,   g_yl);

    cudaFuncSetAttribute((const void*)mma_gemm<0,0,2>, cudaFuncAttributeMaxDynamicSharedMemorySize, SMEM_G);
    cudaFuncSetAttribute((const void*)mma_gemm<3,0,2>, cudaFuncAttributeMaxDynamicSharedMemorySize, SMEM_G);
    cudaFuncSetAttribute((const void*)mma_gemm<4,0,2>, cudaFuncAttributeMaxDynamicSharedMemorySize, SMEM_G);
    cudaFuncSetAttribute((const void*)mma_gemm<4,0,3>, cudaFuncAttributeMaxDynamicSharedMemorySize, SMEM_G);

    split_weights<<<(TOTW + 255)/256, 256>>>(patch_w, in_proj_w, xproj_w,
                                             dtproj_w, out_proj_w, wh, wl);
    im2col_split<<<(MROWS*KPAD + 255)/256, 256>>>(x, imh, iml);

    // patch embed: split-K x2 -> partials (reduce fused into layer-0 LN)
    mma_gemm<4,0,2><<<dim3(3,64,2), 256, SMEM_G>>>(imh, iml, KPAD,
        wh, wl, DMODEL, part, DMODEL, KPAD, nullptr, nullptr, nullptr, 10);

    for (int l=0; l<NLAYER; l++){
        // fused: t = (l==0 ? P0+P1+patch_b : t + P0+P1); LN; split -> xnh/xnl
        if (l == 0)
            ln_split_fused<0><<<1024, 256>>>(part, patch_b, t,
                norm_w, norm_b, xnh, xnl);
        else
            ln_split_fused<1><<<1024, 256>>>(part, nullptr, t,
                norm_w + l*DMODEL, norm_b + l*DMODEL, xnh, xnl);
        // in_proj: 768 CTAs, well balanced -> direct
        mma_gemm<0,0,2><<<dim3(12,64), 256, SMEM_G>>>(xnh, xnl, DMODEL,
            wh + OFF_IN + (size_t)l*SZ_IN, wl + OFF_IN + (size_t)l*SZ_IN, 2*DIN,
            xz, 2*DIN, DMODEL, nullptr, nullptr, nullptr, 0);
        conv_silu_k<<<(MROWS*DIN + 255)/256, 256>>>(xz,
            conv_w + (size_t)l*DIN*4, conv_b + l*DIN, xb, xbh, xbl);
        // x_proj: split-K x4, reduce + split out
        mma_gemm<4,0,2><<<dim3(1,64,4), 256, SMEM_G>>>(xbh, xbl, DIN,
            wh + OFF_XP + (size_t)l*SZ_XP, wl + OFF_XP + (size_t)l*SZ_XP, PROJW,
            part, PROJW, DIN, nullptr, nullptr, nullptr, 6);
        reduce4_split<<<(MROWS*PROJW + 255)/256, 256>>>(part, proj, prh, prl);
        // dt_proj + softplus -> direct
        mma_gemm<3,0,2><<<dim3(6,64), 256, SMEM_G>>>(prh, prl, PROJW,
            wh + OFF_DT + (size_t)l*SZ_DT, wl + OFF_DT + (size_t)l*SZ_DT, DIN,
            dt, DIN, RLOW, dtproj_b + l*DIN, nullptr, nullptr, 0);
        // selective scan
        scan_k<<<dim3(12,32), 256>>>(dt, xb, proj, xz,
            A_log + (size_t)l*DIN*NST, D_ssm + l*DIN, yh, yl);
        // out_proj: split-K x2 -> partials (reduce fused into next LN / final)
        mma_gemm<4,0,3><<<dim3(3,64,2), 256, SMEM_G>>>(yh, yl, DIN,
            wh + OFF_OW + (size_t)l*SZ_OW, wl + OFF_OW + (size_t)l*SZ_OW, DMODEL,
            part, DMODEL, DIN, nullptr, nullptr, nullptr, 12);
    }

    // final LN fused with last residual reduce, then fused pool+classifier
    layernorm_fused<<<1024, 256>>>(part, t, fnorm_w, fnorm_b, xn);
    pool_cls_k<<<BATCH, 384>>>(xn, cls_w, cls_b, out);
}

// round 16
// speedup vs baseline: 1.0837x; 1.0837x over previous
#include <cuda_runtime.h>
#include <cuda_fp16.h>
#include <cstdint>
#include <math.h>

#define BATCH 32
#define LSEQ  256
#define DMODEL 384
#define DIN   768
#define NST   16
#define RLOW  48
#define NLAYER 4
#define NCLS  1000
#define MROWS (BATCH*LSEQ)      // 8192
#define KPATCH 588              // 3*14*14
#define KPAD   592              // padded for 16B-aligned rows
#define PROJW 80                // R + 2*NST

// ---- weight split buffer layout (halves) ----
#define SZ_PW  (DMODEL*KPAD)
#define OFF_IN (SZ_PW)
#define SZ_IN  (2*DIN*DMODEL)
#define OFF_XP (OFF_IN + 4*SZ_IN)
#define SZ_XP  (PROJW*DIN)
#define OFF_DT (OFF_XP + 4*SZ_XP)
#define SZ_DT  (DIN*RLOW)
#define OFF_OW (OFF_DT + 4*SZ_DT)
#define SZ_OW  (DMODEL*DIN)
#define TOTW   (OFF_OW + 4*SZ_OW)

// ---------------- scratch (device globals; no allocation allowed) ----------
__device__ float g_t   [MROWS*DMODEL];
__device__ float g_xn  [MROWS*DMODEL];
__device__ float g_xz  [MROWS*2*DIN];
__device__ float g_xb  [MROWS*DIN];
__device__ float g_proj[MROWS*PROJW];
__device__ float g_dt  [MROWS*DIN];
__device__ float g_pool[BATCH*DMODEL];
__device__ float g_part[4*MROWS*DMODEL];   // split-K partials

__device__ __half g_wh  [TOTW];
__device__ __half g_wl  [TOTW];
__device__ __half g_imh [MROWS*KPAD + 64];
__device__ __half g_iml [MROWS*KPAD + 64];
__device__ __half g_xnh [MROWS*DMODEL];
__device__ __half g_xnl [MROWS*DMODEL];
__device__ __half g_xbh [MROWS*DIN];
__device__ __half g_xbl [MROWS*DIN];
__device__ __half g_prh [MROWS*PROJW];
__device__ __half g_prl [MROWS*PROJW];
__device__ __half g_yh  [MROWS*DIN];
__device__ __half g_yl  [MROWS*DIN];

__device__ __forceinline__ float softplus_f(float v){
    return fmaxf(v, 0.f) + log1pf(expf(-fabsf(v)));
}
__device__ __forceinline__ float silu_f(float v){
    return v / (1.f + __expf(-v));
}
__device__ __forceinline__ void split_f(float v, __half& h, __half& l){
    h = __float2half_rn(v);
    l = __float2half_rn(v - __half2float(h));
}

__device__ __forceinline__ void mma16(float* c, const uint32_t* a, const uint32_t* b){
    asm volatile("mma.sync.aligned.m16n8k16.row.col.f32.f16.f16.f32 "
        "{%0,%1,%2,%3}, {%4,%5,%6,%7}, {%8,%9}, {%0,%1,%2,%3};"
        : "+f"(c[0]), "+f"(c[1]), "+f"(c[2]), "+f"(c[3])
        : "r"(a[0]), "r"(a[1]), "r"(a[2]), "r"(a[3]), "r"(b[0]), "r"(b[1]));
}
__device__ __forceinline__ void ldsm_x4(uint32_t* r, uint32_t addr){
    asm volatile("ldmatrix.sync.aligned.m8n8.x4.shared.b16 {%0,%1,%2,%3}, [%4];"
        : "=r"(r[0]), "=r"(r[1]), "=r"(r[2]), "=r"(r[3]) : "r"(addr));
}
__device__ __forceinline__ uint32_t smem_u32(const void* p){
    uint32_t a;
    asm("{ .reg .u64 t; cvta.to.shared.u64 t, %1; cvt.u32.u64 %0, t; }" : "=r"(a) : "l"(p));
    return a;
}
__device__ __forceinline__ void cp_async16(uint32_t dst, const void* src, int bytes){
    asm volatile("cp.async.ca.shared.global [%0], [%1], 16, %2;"
        :: "r"(dst), "l"(src), "r"(bytes) : "memory");
}
#define CP_COMMIT() asm volatile("cp.async.commit_group;" ::: "memory")
#define CP_WAIT0()  asm volatile("cp.async.wait_group 0;"  ::: "memory")

// ---------------- weight split: fp32 -> (hi, lo) fp16 ----------------------
__global__ void split_weights(const float* __restrict__ pw,
                              const float* __restrict__ inw,
                              const float* __restrict__ xpw,
                              const float* __restrict__ dtw,
                              const float* __restrict__ ow,
                              __half* __restrict__ wh, __half* __restrict__ wl)
{
    int i = blockIdx.x*blockDim.x + threadIdx.x;
    if (i >= TOTW) return;
    float v;
    if (i < OFF_IN){
        int row = i / KPAD, col = i - row*KPAD;
        v = (col < KPATCH) ? pw[row*KPATCH + col] : 0.f;
    }
    else if (i < OFF_XP) v = inw[i-OFF_IN];
    else if (i < OFF_DT) v = xpw[i-OFF_XP];
    else if (i < OFF_OW) v = dtw[i-OFF_DT];
    else                 v = ow [i-OFF_OW];
    __half h, l; split_f(v, h, l);
    wh[i] = h; wl[i] = l;
}

// ---------------- im2col gather + split (patch embed A operand) ------------
__global__ void im2col_split(const float* __restrict__ X,
                             __half* __restrict__ oh, __half* __restrict__ ol)
{
    int idx = blockIdx.x*blockDim.x + threadIdx.x;
    if (idx >= MROWS*KPAD) return;
    int m = idx / KPAD, k = idx - m*KPAD;
    float v = 0.f;
    if (k < KPATCH){
        int b = m >> 8, l = m & 255;
        int py = l >> 4, px = l & 15;
        int cc = k / 196, rem = k - cc*196;
        int ky = rem / 14, kx = rem - ky*14;
        v = X[((size_t)(b*3 + cc)*224 + (py*14+ky))*224 + (px*14+kx)];
    }
    __half h, l2; split_f(v, h, l2);
    oh[idx] = h; ol[idx] = l2;
}

// =================== fp16-split GEMM, cp.async + ldmatrix ===================
#define KCH   32
#define HSTR  40
#define SUBT  (128*HSTR)
#define STAGE_H (4*SUBT)
#define SMEM_G  (2*STAGE_H*2)

// MODE 0: plain  1: += res  2: + bias[n]  3: softplus(. + bias[n])
// MODE 4: split-K partial
template<int MODE, int SPLIT, int NPROD>
__global__ void __launch_bounds__(256,2) mma_gemm(
        const __half* __restrict__ Ah_g, const __half* __restrict__ Al_g, int lda,
        const __half* __restrict__ Bh_g, const __half* __restrict__ Bl_g, int Nrows,
        float* __restrict__ C, int ldc, int Kd,
        const float* __restrict__ aux,
        __half* __restrict__ Ch, __half* __restrict__ Cl,
        int cpz)
{
    extern __shared__ __half smem[];
    const uint32_t sb = smem_u32(smem);
    const int tid = threadIdx.x;
    const int wid = tid >> 5, lane = tid & 31;
    const int wm = wid & 1, wn = wid >> 1;
    const int g = lane >> 2, t = lane & 3;
    const int bm = blockIdx.y << 7, bn = blockIdx.x << 7;
    const int NC = (Kd + KCH - 1) / KCH;

    int cbeg = 0, cend = NC;
    if (MODE == 4){
        cbeg = blockIdx.z * cpz;
        cend = min(NC, cbeg + cpz);
        C += (size_t)blockIdx.z * MROWS * ldc;
    }

    const int ldrow = (lane & 7) + ((lane >> 3) & 1)*8;
    const int ldk   = (lane >> 4)*8;
    const uint32_t offA = (uint32_t)(((wm*64 + ldrow)*HSTR + ldk)*2);
    const uint32_t offB = (uint32_t)(((wn*32 + ldrow)*HSTR + ldk)*2 + 2*SUBT*2);

    float acc[4][4][4];
    #pragma unroll
    for (int i=0;i<4;i++)
        #pragma unroll
        for (int j=0;j<4;j++)
            #pragma unroll
            for (int q=0;q<4;q++) acc[i][j][q]=0.f;

    constexpr int NVEC = (NPROD == 3) ? 8 : 6;
    auto issue = [&](int j){
        const int k0 = j*KCH;
        const uint32_t stage = sb + (uint32_t)((j&1)*STAGE_H)*2u;
        #pragma unroll
        for (int i=0;i<NVEC;i++){
            int e    = tid + (i<<8);
            int subi = e >> 9;
            int sub  = (NPROD == 3) ? subi : (subi == 0 ? 0 : subi + 1); // {Ah,Bh,Bl}
            int r    = (e & 511) >> 2;
            int c8   = e & 3;
            int gk   = k0 + (c8<<3);
            int bytes = (Kd - gk)*2;
            bytes = bytes < 0 ? 0 : (bytes > 16 ? 16 : bytes);
            const __half* src;
            if (sub < 2){
                src = (sub ? Al_g : Ah_g) + (size_t)(bm + r)*lda + gk;
            } else {
                int gr = bn + r;
                if (gr >= Nrows) bytes = 0;
                src = (sub == 3 ? Bl_g : Bh_g);
                if (bytes) src += (size_t)gr*Kd + gk;
            }
            uint32_t dst = stage + (uint32_t)(sub*SUBT + r*HSTR + (c8<<3))*2u;
            cp_async16(dst, src, bytes);
        }
        CP_COMMIT();
    };

    issue(cbeg);

    for (int j=cbeg;j<cend;j++){
        CP_WAIT0();
        __syncthreads();
        if (j+1 < cend) issue(j+1);

        const uint32_t stage = sb + (uint32_t)((j&1)*STAGE_H)*2u;
        const uint32_t aBase = stage + offA;
        const uint32_t bBase = stage + offB;

        #pragma unroll
        for (int ks=0; ks<2; ks++){
            const uint32_t kof = (uint32_t)(ks*16*2);
            uint32_t ah[4][4], al[4][4];
            #pragma unroll
            for (int im=0; im<4; im++){
                uint32_t a = aBase + (uint32_t)(im*16*HSTR*2) + kof;
                ldsm_x4(ah[im], a);
                if (NPROD == 3) ldsm_x4(al[im], a + (uint32_t)(SUBT*2));
            }
            uint32_t bh[4][2], bl[4][2];
            #pragma unroll
            for (int p=0; p<2; p++){
                uint32_t b = bBase + (uint32_t)(p*16*HSTR*2) + kof;
                uint32_t r[4];
                ldsm_x4(r, b);
                bh[2*p][0]=r[0]; bh[2*p+1][0]=r[1]; bh[2*p][1]=r[2]; bh[2*p+1][1]=r[3];
                ldsm_x4(r, b + (uint32_t)(SUBT*2));
                bl[2*p][0]=r[0]; bl[2*p+1][0]=r[1]; bl[2*p][1]=r[2]; bl[2*p+1][1]=r[3];
            }
            #pragma unroll
            for (int im=0; im<4; im++)
                #pragma unroll
                for (int in_=0; in_<4; in_++)
                    mma16(acc[im][in_], ah[im], bh[in_]);
            #pragma unroll
            for (int im=0; im<4; im++)
                #pragma unroll
                for (int in_=0; in_<4; in_++)
                    mma16(acc[im][in_], ah[im], bl[in_]);
            if (NPROD == 3){
                #pragma unroll
                for (int im=0; im<4; im++)
                    #pragma unroll
                    for (int in_=0; in_<4; in_++)
                        mma16(acc[im][in_], al[im], bh[in_]);
            }
        }
    }

    #pragma unroll
    for (int im=0; im<4; im++){
        int r0 = bm + wm*64 + im*16 + g;
        #pragma unroll
        for (int in_=0; in_<4; in_++){
            int cc = bn + wn*32 + in_*8 + (t<<1);
            if (cc < Nrows){
                float2 v0 = make_float2(acc[im][in_][0], acc[im][in_][1]);
                float2 v1 = make_float2(acc[im][in_][2], acc[im][in_][3]);
                if (MODE==1){
                    float2 r = *(const float2*)&aux[(size_t)r0*ldc + cc];
                    v0.x += r.x; v0.y += r.y;
                    float2 s = *(const float2*)&aux[(size_t)(r0+8)*ldc + cc];
                    v1.x += s.x; v1.y += s.y;
                } else if (MODE==2 || MODE==3){
                    float2 b = *(const float2*)&aux[cc];
                    v0.x += b.x; v0.y += b.y;
                    v1.x += b.x; v1.y += b.y;
                    if (MODE==3){
                        v0.x = softplus_f(v0.x); v0.y = softplus_f(v0.y);
                        v1.x = softplus_f(v1.x); v1.y = softplus_f(v1.y);
                    }
                }
                *(float2*)&C[(size_t)r0*ldc + cc]     = v0;
                *(float2*)&C[(size_t)(r0+8)*ldc + cc] = v1;
                if (SPLIT){
                    __half h0,l0,h1,l1;
                    split_f(v0.x, h0, l0); split_f(v0.y, h1, l1);
                    *(__half2*)&Ch[(size_t)r0*ldc + cc] = __halves2half2(h0,h1);
                    *(__half2*)&Cl[(size_t)r0*ldc + cc] = __halves2half2(l0,l1);
                    split_f(v1.x, h0, l0); split_f(v1.y, h1, l1);
                    *(__half2*)&Ch[(size_t)(r0+8)*ldc + cc] = __halves2half2(h0,h1);
                    *(__half2*)&Cl[(size_t)(r0+8)*ldc + cc] = __halves2half2(l0,l1);
                }
            }
        }
    }
}

// ---------------- split-K reduce (x_proj only) -------------------------------
__global__ void reduce4_split(const float* __restrict__ P,
                              float* __restrict__ proj,
                              __half* __restrict__ ph, __half* __restrict__ pl)
{
    int i = blockIdx.x*blockDim.x + threadIdx.x;
    if (i >= MROWS*PROJW) return;
    const int N = MROWS*PROJW;
    float s = (P[i] + P[N + i]) + (P[2*N + i] + P[3*N + i]);
    proj[i] = s;
    __half h, l; split_f(s, h, l);
    ph[i] = h; pl[i] = l;
}

// ------- fused LN kernels: consume split-K partials, produce t & splits -----
// MODE_T 0: t_new = P0 + P1 + bias[c]   (patch output)
//        1: t_new = t + P0 + P1         (residual accumulate)
template<int MODE_T>
__global__ void ln_split_fused(const float* __restrict__ P,
                               const float* __restrict__ bias,
                               float* __restrict__ tbuf,
                               const float* __restrict__ w,
                               const float* __restrict__ b,
                               __half* __restrict__ oh, __half* __restrict__ ol)
{
    int row  = blockIdx.x*8 + (threadIdx.x >> 5);
    int lane = threadIdx.x & 31;
    const size_t rb = (size_t)row*DMODEL;
    float v[12]; float s=0.f, sq=0.f;
    #pragma unroll
    for (int i=0;i<12;i++){
        int c = lane + i*32;
        float tn = P[rb + c] + P[(size_t)MROWS*DMODEL + rb + c];
        if (MODE_T == 0) tn += bias[c];
        else             tn += tbuf[rb + c];
        tbuf[rb + c] = tn;
        v[i] = tn; s += tn; sq += tn*tn;
    }
    #pragma unroll
    for (int o=16;o;o>>=1){
        s  += __shfl_xor_sync(0xffffffffu, s,  o);
        sq += __shfl_xor_sync(0xffffffffu, sq, o);
    }
    float m   = s  * (1.f/DMODEL);
    float var = sq * (1.f/DMODEL) - m*m;
    float r   = rsqrtf(var + 1e-5f);
    #pragma unroll
    for (int i=0;i<12;i++){
        int c = lane + i*32;
        float o = (v[i]-m)*r*w[c] + b[c];
        __half h, l; split_f(o, h, l);
        oh[rb + c] = h;
        ol[rb + c] = l;
    }
}

// final LN fused with residual reduce: xn = LN(t + P0 + P1)
__global__ void layernorm_fused(const float* __restrict__ P,
                                const float* __restrict__ tbuf,
                                const float* __restrict__ w,
                                const float* __restrict__ b,
                                float* __restrict__ out)
{
    int row  = blockIdx.x*8 + (threadIdx.x >> 5);
    int lane = threadIdx.x & 31;
    const size_t rb = (size_t)row*DMODEL;
    float v[12]; float s=0.f, sq=0.f;
    #pragma unroll
    for (int i=0;i<12;i++){
        int c = lane + i*32;
        float tn = tbuf[rb + c] + P[rb + c] + P[(size_t)MROWS*DMODEL + rb + c];
        v[i] = tn; s += tn; sq += tn*tn;
    }
    #pragma unroll
    for (int o=16;o;o>>=1){
        s  += __shfl_xor_sync(0xffffffffu, s,  o);
        sq += __shfl_xor_sync(0xffffffffu, sq, o);
    }
    float m   = s  * (1.f/DMODEL);
    float var = sq * (1.f/DMODEL) - m*m;
    float r   = rsqrtf(var + 1e-5f);
    #pragma unroll
    for (int i=0;i<12;i++){
        int c = lane + i*32;
        out[rb + c] = (v[i]-m)*r*w[c] + b[c];
    }
}

// ---------------- causal depthwise conv1d + bias + silu, split out ---------
__global__ void conv_silu_k(const float* __restrict__ xz,
                            const float* __restrict__ cw,
                            const float* __restrict__ cb,
                            float* __restrict__ xb,
                            __half* __restrict__ xbh, __half* __restrict__ xbl)
{
    int idx = blockIdx.x*blockDim.x + threadIdx.x;
    if (idx >= MROWS*DIN) return;
    int d  = idx % DIN;
    int bl_ = idx / DIN;
    int l  = bl_ & 255;
    int b  = bl_ >> 8;
    float acc = cb[d];
    #pragma unroll
    for (int j=0;j<4;j++){
        int ls = l - 3 + j;
        if (ls >= 0)
            acc = fmaf(xz[(size_t)(b*LSEQ+ls)*(2*DIN) + d], cw[d*4+j], acc);
    }
    float o = silu_f(acc);
    xb[idx] = o;
    __half h, lo; split_f(o, h, lo);
    xbh[idx] = h; xbl[idx] = lo;
}

// ---------------- selective scan: thread per (b,d, n-quad) ------------------
__global__ void __launch_bounds__(256) scan_k(
                       const float* __restrict__ dtp,
                       const float* __restrict__ xbp,
                       const float* __restrict__ proj,
                       const float* __restrict__ xz,
                       const float* __restrict__ A_log,
                       const float* __restrict__ Dp,
                       __half* __restrict__ yh, __half* __restrict__ yl)
{
    const int tid = threadIdx.x;
    const int nq  = tid & 3;
    const int dl  = tid >> 2;
    const int d   = blockIdx.x*64 + dl;
    const int b   = blockIdx.y;

    float A[4];
    bool okf = true;
    #pragma unroll
    for (int j=0;j<4;j++){
        int n = nq*4 + j;
        A[j] = -__expf(A_log[d*NST + n]);
        float kf = (float)(n+1);
        okf = okf && (fabsf(-A[j] - kf) <= 1e-5f*kf);
    }
    const bool fast = __all_sync(0xffffffffu, okf);
    const float Dd = Dp[d];
    float h0=0.f, h1=0.f, h2=0.f, h3=0.f;
    const size_t base = (size_t)b*LSEQ;

    size_t row = base;
    float dt_c = dtp[row*DIN + d];
    float xv_c = xbp[row*DIN + d];
    float4 B_c = *(const float4*)&proj[row*PROJW + RLOW + nq*4];
    float4 C_c = *(const float4*)&proj[row*PROJW + RLOW + NST + nq*4];

    for (int l=0; l<LSEQ; l++){
        row = base + l;
        float dt = dt_c, xv = xv_c;
        float4 Bv = B_c, Cv = C_c;
        if (l+1 < LSEQ){
            size_t r2 = row + 1;
            dt_c = dtp[r2*DIN + d];
            xv_c = xbp[r2*DIN + d];
            B_c  = *(const float4*)&proj[r2*PROJW + RLOW + nq*4];
            C_c  = *(const float4*)&proj[r2*PROJW + RLOW + NST + nq*4];
        }
        float dtx = dt*xv;
        if (fast){
            float e1 = __expf(-dt);
            float e2 = e1*e1;
            float e4 = e2*e2;
            float e8 = e4*e4;
            float bp = 1.f;
            if (nq & 1) bp = e4;
            if (nq & 2) bp *= e8;
            float r = bp*e1;
            h0 = fmaf(h0, r, dtx*Bv.x); r *= e1;
            h1 = fmaf(h1, r, dtx*Bv.y); r *= e1;
            h2 = fmaf(h2, r, dtx*Bv.z); r *= e1;
            h3 = fmaf(h3, r, dtx*Bv.w);
        } else {
            h0 = fmaf(h0, __expf(dt*A[0]), dtx*Bv.x);
            h1 = fmaf(h1, __expf(dt*A[1]), dtx*Bv.y);
            h2 = fmaf(h2, __expf(dt*A[2]), dtx*Bv.z);
            h3 = fmaf(h3, __expf(dt*A[3]), dtx*Bv.w);
        }
        float p = h0*Cv.x + h1*Cv.y + h2*Cv.z + h3*Cv.w;
        p += __shfl_xor_sync(0xffffffffu, p, 1);
        p += __shfl_xor_sync(0xffffffffu, p, 2);
        if (nq == 0){
            float z = xz[row*(2*DIN) + DIN + d];
            float yv = (p + xv*Dd) * silu_f(z);
            __half hh, ll; split_f(yv, hh, ll);
            yh[row*DIN + d] = hh;
            yl[row*DIN + d] = ll;
        }
    }
}

// ---------------- mean-pool over L ------------------------------------------
__global__ void pool_k(const float* __restrict__ ln, float* __restrict__ out)
{
    int b = blockIdx.x;
    int d = threadIdx.x;
    float s = 0.f;
    for (int l=0;l<LSEQ;l++)
        s += ln[(size_t)(b*LSEQ+l)*DMODEL + d];
    out[b*DMODEL + d] = s * (1.f/LSEQ);
}

// ---------------- classifier head -------------------------------------------
__global__ void classifier_k(const float* __restrict__ pool,
                             const float* __restrict__ w,
                             const float* __restrict__ bias,
                             float* __restrict__ out)
{
    int idx = blockIdx.x*blockDim.x + threadIdx.x;
    if (idx >= NCLS*BATCH) return;
    int b = idx & 31;
    int n = idx >> 5;
    const float* pr = pool + b*DMODEL;
    const float* wr = w + (size_t)n*DMODEL;
    float acc = bias[n];
    #pragma unroll 4
    for (int k=0;k<DMODEL;k++)
        acc = fmaf(pr[k], wr[k], acc);
    out[b*NCLS + n] = acc;
}

// ---------------- launch -----------------------------------------------------
extern "C" void kernel_launch(void* const* d_in, const int* in_sizes, int n_in,
                              void* d_out, int out_size)
{
    const float* x         = (const float*)d_in[0];
    const float* patch_w   = (const float*)d_in[1];
    const float* patch_b   = (const float*)d_in[2];
    const float* norm_w    = (const float*)d_in[3];
    const float* norm_b    = (const float*)d_in[4];
    const float* in_proj_w = (const float*)d_in[5];
    const float* conv_w    = (const float*)d_in[6];
    const float* conv_b    = (const float*)d_in[7];
    const float* A_log     = (const float*)d_in[8];
    const float* D_ssm     = (const float*)d_in[9];
    const float* xproj_w   = (const float*)d_in[10];
    const float* dtproj_w  = (const float*)d_in[11];
    const float* dtproj_b  = (const float*)d_in[12];
    const float* out_proj_w= (const float*)d_in[13];
    const float* fnorm_w   = (const float*)d_in[14];
    const float* fnorm_b   = (const float*)d_in[15];
    const float* cls_w     = (const float*)d_in[16];
    const float* cls_b     = (const float*)d_in[17];
    float* out = (float*)d_out;

    float *t, *xn, *xz, *xb, *proj, *dt, *pool, *part;
    __half *wh, *wl, *imh, *iml, *xnh, *xnl, *xbh, *xbl, *prh, *prl, *yh, *yl;
    cudaGetSymbolAddress((void**)&t,    g_t);
    cudaGetSymbolAddress((void**)&xn,   g_xn);
    cudaGetSymbolAddress((void**)&xz,   g_xz);
    cudaGetSymbolAddress((void**)&xb,   g_xb);
    cudaGetSymbolAddress((void**)&proj, g_proj);
    cudaGetSymbolAddress((void**)&dt,   g_dt);
    cudaGetSymbolAddress((void**)&pool, g_pool);
    cudaGetSymbolAddress((void**)&part, g_part);
    cudaGetSymbolAddress((void**)&wh,   g_wh);
    cudaGetSymbolAddress((void**)&wl,   g_wl);
    cudaGetSymbolAddress((void**)&imh,  g_imh);
    cudaGetSymbolAddress((void**)&iml,  g_iml);
    cudaGetSymbolAddress((void**)&xnh,  g_xnh);
    cudaGetSymbolAddress((void**)&xnl,  g_xnl);
    cudaGetSymbolAddress((void**)&xbh,  g_xbh);
    cudaGetSymbolAddress((void**)&xbl,  g_xbl);
    cudaGetSymbolAddress((void**)&prh,  g_prh);
    cudaGetSymbolAddress((void**)&prl,  g_prl);
    cudaGetSymbolAddress((void**)&yh,   g_yh);
    cudaGetSymbolAddress((void**)&yl,   g_yl);

    cudaFuncSetAttribute((const void*)mma_gemm<0,0,2>, cudaFuncAttributeMaxDynamicSharedMemorySize, SMEM_G);
    cudaFuncSetAttribute((const void*)mma_gemm<3,0,2>, cudaFuncAttributeMaxDynamicSharedMemorySize, SMEM_G);
    cudaFuncSetAttribute((const void*)mma_gemm<4,0,2>, cudaFuncAttributeMaxDynamicSharedMemorySize, SMEM_G);
    cudaFuncSetAttribute((const void*)mma_gemm<4,0,3>, cudaFuncAttributeMaxDynamicSharedMemorySize, SMEM_G);

    split_weights<<<(TOTW + 255)/256, 256>>>(patch_w, in_proj_w, xproj_w,
                                             dtproj_w, out_proj_w, wh, wl);
    im2col_split<<<(MROWS*KPAD + 255)/256, 256>>>(x, imh, iml);

    // patch embed: split-K x2 -> partials (reduce fused into layer-0 LN)
    mma_gemm<4,0,2><<<dim3(3,64,2), 256, SMEM_G>>>(imh, iml, KPAD,
        wh, wl, DMODEL, part, DMODEL, KPAD, nullptr, nullptr, nullptr, 10);

    for (int l=0; l<NLAYER; l++){
        // fused: t = (l==0 ? P0+P1+patch_b : t + P0+P1); LN; split -> xnh/xnl
        if (l == 0)
            ln_split_fused<0><<<1024, 256>>>(part, patch_b, t,
                norm_w, norm_b, xnh, xnl);
        else
            ln_split_fused<1><<<1024, 256>>>(part, nullptr, t,
                norm_w + l*DMODEL, norm_b + l*DMODEL, xnh, xnl);
        // in_proj: 768 CTAs, well balanced -> direct
        mma_gemm<0,0,2><<<dim3(12,64), 256, SMEM_G>>>(xnh, xnl, DMODEL,
            wh + OFF_IN + (size_t)l*SZ_IN, wl + OFF_IN + (size_t)l*SZ_IN, 2*DIN,
            xz, 2*DIN, DMODEL, nullptr, nullptr, nullptr, 0);
        conv_silu_k<<<(MROWS*DIN + 255)/256, 256>>>(xz,
            conv_w + (size_t)l*DIN*4, conv_b + l*DIN, xb, xbh, xbl);
        // x_proj: split-K x4, reduce + split out
        mma_gemm<4,0,2><<<dim3(1,64,4), 256, SMEM_G>>>(xbh, xbl, DIN,
            wh + OFF_XP + (size_t)l*SZ_XP, wl + OFF_XP + (size_t)l*SZ_XP, PROJW,
            part, PROJW, DIN, nullptr, nullptr, nullptr, 6);
        reduce4_split<<<(MROWS*PROJW + 255)/256, 256>>>(part, proj, prh, prl);
        // dt_proj + softplus -> direct
        mma_gemm<3,0,2><<<dim3(6,64), 256, SMEM_G>>>(prh, prl, PROJW,
            wh + OFF_DT + (size_t)l*SZ_DT, wl + OFF_DT + (size_t)l*SZ_DT, DIN,
            dt, DIN, RLOW, dtproj_b + l*DIN, nullptr, nullptr, 0);
        // selective scan
        scan_k<<<dim3(12,32), 256>>>(dt, xb, proj, xz,
            A_log + (size_t)l*DIN*NST, D_ssm + l*DIN, yh, yl);
        // out_proj: split-K x2 -> partials (reduce fused into next LN / final)
        mma_gemm<4,0,3><<<dim3(3,64,2), 256, SMEM_G>>>(yh, yl, DIN,
            wh + OFF_OW + (size_t)l*SZ_OW, wl + OFF_OW + (size_t)l*SZ_OW, DMODEL,
            part, DMODEL, DIN, nullptr, nullptr, nullptr, 12);
    }

    // final LN fused with last residual reduce
    layernorm_fused<<<1024, 256>>>(part, t, fnorm_w, fnorm_b, xn);
    pool_k<<<BATCH, DMODEL>>>(xn, pool);
    classifier_k<<<(NCLS*BATCH + 255)/256, 256>>>(pool, cls_w, cls_b, out);
}

// round 17
// speedup vs baseline: 1.1021x; 1.0169x over previous
#include <cuda_runtime.h>
#include <cuda_fp16.h>
#include <cstdint>
#include <math.h>

#define BATCH 32
#define LSEQ  256
#define DMODEL 384
#define DIN   768
#define NST   16
#define RLOW  48
#define NLAYER 4
#define NCLS  1000
#define MROWS (BATCH*LSEQ)      // 8192
#define KPATCH 588              // 3*14*14
#define KPAD   592              // padded for 16B-aligned rows
#define PROJW 80                // R + 2*NST

// ---- weight split buffer layout (halves) ----
#define SZ_PW  (DMODEL*KPAD)
#define OFF_IN (SZ_PW)
#define SZ_IN  (2*DIN*DMODEL)
#define OFF_XP (OFF_IN + 4*SZ_IN)
#define SZ_XP  (PROJW*DIN)
#define OFF_DT (OFF_XP + 4*SZ_XP)
#define SZ_DT  (DIN*RLOW)
#define OFF_OW (OFF_DT + 4*SZ_DT)
#define SZ_OW  (DMODEL*DIN)
#define TOTW   (OFF_OW + 4*SZ_OW)

// ---------------- scratch (device globals; no allocation allowed) ----------
__device__ float g_t   [MROWS*DMODEL];
__device__ float g_xn  [MROWS*DMODEL];
__device__ float g_xz  [MROWS*2*DIN];
__device__ float g_xb  [MROWS*DIN];
__device__ float g_proj[MROWS*PROJW];
__device__ float g_dt  [MROWS*DIN];
__device__ float g_pool[BATCH*DMODEL];
__device__ float g_part[4*MROWS*DMODEL];   // split-K partials

__device__ __half g_wh  [TOTW];
__device__ __half g_wl  [TOTW];
__device__ __half g_imh [MROWS*KPAD + 64];
__device__ __half g_iml [MROWS*KPAD + 64];
__device__ __half g_xnh [MROWS*DMODEL];
__device__ __half g_xnl [MROWS*DMODEL];
__device__ __half g_xbh [MROWS*DIN];
__device__ __half g_xbl [MROWS*DIN];
__device__ __half g_prh [MROWS*PROJW];
__device__ __half g_prl [MROWS*PROJW];
__device__ __half g_yh  [MROWS*DIN];
__device__ __half g_yl  [MROWS*DIN];

__device__ __forceinline__ float softplus_f(float v){
    return fmaxf(v, 0.f) + log1pf(expf(-fabsf(v)));
}
__device__ __forceinline__ float silu_f(float v){
    return v / (1.f + __expf(-v));
}
__device__ __forceinline__ void split_f(float v, __half& h, __half& l){
    h = __float2half_rn(v);
    l = __float2half_rn(v - __half2float(h));
}

__device__ __forceinline__ void mma16(float* c, const uint32_t* a, const uint32_t* b){
    asm volatile("mma.sync.aligned.m16n8k16.row.col.f32.f16.f16.f32 "
        "{%0,%1,%2,%3}, {%4,%5,%6,%7}, {%8,%9}, {%0,%1,%2,%3};"
        : "+f"(c[0]), "+f"(c[1]), "+f"(c[2]), "+f"(c[3])
        : "r"(a[0]), "r"(a[1]), "r"(a[2]), "r"(a[3]), "r"(b[0]), "r"(b[1]));
}
__device__ __forceinline__ void ldsm_x4(uint32_t* r, uint32_t addr){
    asm volatile("ldmatrix.sync.aligned.m8n8.x4.shared.b16 {%0,%1,%2,%3}, [%4];"
        : "=r"(r[0]), "=r"(r[1]), "=r"(r[2]), "=r"(r[3]) : "r"(addr));
}
__device__ __forceinline__ uint32_t smem_u32(const void* p){
    uint32_t a;
    asm("{ .reg .u64 t; cvta.to.shared.u64 t, %1; cvt.u32.u64 %0, t; }" : "=r"(a) : "l"(p));
    return a;
}
__device__ __forceinline__ void cp_async16(uint32_t dst, const void* src, int bytes){
    asm volatile("cp.async.ca.shared.global [%0], [%1], 16, %2;"
        :: "r"(dst), "l"(src), "r"(bytes) : "memory");
}
#define CP_COMMIT() asm volatile("cp.async.commit_group;" ::: "memory")
#define CP_WAIT0()  asm volatile("cp.async.wait_group 0;"  ::: "memory")

// ---------------- weight split: fp32 -> (hi, lo) fp16 ----------------------
__global__ void split_weights(const float* __restrict__ pw,
                              const float* __restrict__ inw,
                              const float* __restrict__ xpw,
                              const float* __restrict__ dtw,
                              const float* __restrict__ ow,
                              __half* __restrict__ wh, __half* __restrict__ wl)
{
    int i = blockIdx.x*blockDim.x + threadIdx.x;
    if (i >= TOTW) return;
    float v;
    if (i < OFF_IN){
        int row = i / KPAD, col = i - row*KPAD;
        v = (col < KPATCH) ? pw[row*KPATCH + col] : 0.f;
    }
    else if (i < OFF_XP) v = inw[i-OFF_IN];
    else if (i < OFF_DT) v = xpw[i-OFF_XP];
    else if (i < OFF_OW) v = dtw[i-OFF_DT];
    else                 v = ow [i-OFF_OW];
    __half h, l; split_f(v, h, l);
    wh[i] = h; wl[i] = l;
}

// ---------------- im2col gather + split (patch embed A operand) ------------
__global__ void im2col_split(const float* __restrict__ X,
                             __half* __restrict__ oh, __half* __restrict__ ol)
{
    int idx = blockIdx.x*blockDim.x + threadIdx.x;
    if (idx >= MROWS*KPAD) return;
    int m = idx / KPAD, k = idx - m*KPAD;
    float v = 0.f;
    if (k < KPATCH){
        int b = m >> 8, l = m & 255;
        int py = l >> 4, px = l & 15;
        int cc = k / 196, rem = k - cc*196;
        int ky = rem / 14, kx = rem - ky*14;
        v = X[((size_t)(b*3 + cc)*224 + (py*14+ky))*224 + (px*14+kx)];
    }
    __half h, l2; split_f(v, h, l2);
    oh[idx] = h; ol[idx] = l2;
}

// =================== fp16-split GEMM, cp.async + ldmatrix ===================
#define KCH   32
#define HSTR  40
#define SUBT  (128*HSTR)
#define STAGE_H (4*SUBT)
#define SMEM_G  (2*STAGE_H*2)

// MODE 0: plain  1: += res  2: + bias[n]  3: softplus(. + bias[n])
// MODE 4: split-K partial
template<int MODE, int SPLIT, int NPROD>
__global__ void __launch_bounds__(256,2) mma_gemm(
        const __half* __restrict__ Ah_g, const __half* __restrict__ Al_g, int lda,
        const __half* __restrict__ Bh_g, const __half* __restrict__ Bl_g, int Nrows,
        float* __restrict__ C, int ldc, int Kd,
        const float* __restrict__ aux,
        __half* __restrict__ Ch, __half* __restrict__ Cl,
        int cpz)
{
    extern __shared__ __half smem[];
    const uint32_t sb = smem_u32(smem);
    const int tid = threadIdx.x;
    const int wid = tid >> 5, lane = tid & 31;
    const int wm = wid & 1, wn = wid >> 1;
    const int g = lane >> 2, t = lane & 3;
    const int bm = blockIdx.y << 7, bn = blockIdx.x << 7;
    const int NC = (Kd + KCH - 1) / KCH;

    int cbeg = 0, cend = NC;
    if (MODE == 4){
        cbeg = blockIdx.z * cpz;
        cend = min(NC, cbeg + cpz);
        C += (size_t)blockIdx.z * MROWS * ldc;
    }

    const int ldrow = (lane & 7) + ((lane >> 3) & 1)*8;
    const int ldk   = (lane >> 4)*8;
    const uint32_t offA = (uint32_t)(((wm*64 + ldrow)*HSTR + ldk)*2);
    const uint32_t offB = (uint32_t)(((wn*32 + ldrow)*HSTR + ldk)*2 + 2*SUBT*2);

    float acc[4][4][4];
    #pragma unroll
    for (int i=0;i<4;i++)
        #pragma unroll
        for (int j=0;j<4;j++)
            #pragma unroll
            for (int q=0;q<4;q++) acc[i][j][q]=0.f;

    constexpr int NVEC = (NPROD == 3) ? 8 : 6;
    auto issue = [&](int j){
        const int k0 = j*KCH;
        const uint32_t stage = sb + (uint32_t)((j&1)*STAGE_H)*2u;
        #pragma unroll
        for (int i=0;i<NVEC;i++){
            int e    = tid + (i<<8);
            int subi = e >> 9;
            int sub  = (NPROD == 3) ? subi : (subi == 0 ? 0 : subi + 1); // {Ah,Bh,Bl}
            int r    = (e & 511) >> 2;
            int c8   = e & 3;
            int gk   = k0 + (c8<<3);
            int bytes = (Kd - gk)*2;
            bytes = bytes < 0 ? 0 : (bytes > 16 ? 16 : bytes);
            const __half* src;
            if (sub < 2){
                src = (sub ? Al_g : Ah_g) + (size_t)(bm + r)*lda + gk;
            } else {
                int gr = bn + r;
                if (gr >= Nrows) bytes = 0;
                src = (sub == 3 ? Bl_g : Bh_g);
                if (bytes) src += (size_t)gr*Kd + gk;
            }
            uint32_t dst = stage + (uint32_t)(sub*SUBT + r*HSTR + (c8<<3))*2u;
            cp_async16(dst, src, bytes);
        }
        CP_COMMIT();
    };

    issue(cbeg);

    for (int j=cbeg;j<cend;j++){
        CP_WAIT0();
        __syncthreads();
        if (j+1 < cend) issue(j+1);

        const uint32_t stage = sb + (uint32_t)((j&1)*STAGE_H)*2u;
        const uint32_t aBase = stage + offA;
        const uint32_t bBase = stage + offB;

        #pragma unroll
        for (int ks=0; ks<2; ks++){
            const uint32_t kof = (uint32_t)(ks*16*2);
            uint32_t ah[4][4], al[4][4];
            #pragma unroll
            for (int im=0; im<4; im++){
                uint32_t a = aBase + (uint32_t)(im*16*HSTR*2) + kof;
                ldsm_x4(ah[im], a);
                if (NPROD == 3) ldsm_x4(al[im], a + (uint32_t)(SUBT*2));
            }
            uint32_t bh[4][2], bl[4][2];
            #pragma unroll
            for (int p=0; p<2; p++){
                uint32_t b = bBase + (uint32_t)(p*16*HSTR*2) + kof;
                uint32_t r[4];
                ldsm_x4(r, b);
                bh[2*p][0]=r[0]; bh[2*p+1][0]=r[1]; bh[2*p][1]=r[2]; bh[2*p+1][1]=r[3];
                ldsm_x4(r, b + (uint32_t)(SUBT*2));
                bl[2*p][0]=r[0]; bl[2*p+1][0]=r[1]; bl[2*p][1]=r[2]; bl[2*p+1][1]=r[3];
            }
            #pragma unroll
            for (int im=0; im<4; im++)
                #pragma unroll
                for (int in_=0; in_<4; in_++)
                    mma16(acc[im][in_], ah[im], bh[in_]);
            #pragma unroll
            for (int im=0; im<4; im++)
                #pragma unroll
                for (int in_=0; in_<4; in_++)
                    mma16(acc[im][in_], ah[im], bl[in_]);
            if (NPROD == 3){
                #pragma unroll
                for (int im=0; im<4; im++)
                    #pragma unroll
                    for (int in_=0; in_<4; in_++)
                        mma16(acc[im][in_], al[im], bh[in_]);
            }
        }
    }

    #pragma unroll
    for (int im=0; im<4; im++){
        int r0 = bm + wm*64 + im*16 + g;
        #pragma unroll
        for (int in_=0; in_<4; in_++){
            int cc = bn + wn*32 + in_*8 + (t<<1);
            if (cc < Nrows){
                float2 v0 = make_float2(acc[im][in_][0], acc[im][in_][1]);
                float2 v1 = make_float2(acc[im][in_][2], acc[im][in_][3]);
                if (MODE==1){
                    float2 r = *(const float2*)&aux[(size_t)r0*ldc + cc];
                    v0.x += r.x; v0.y += r.y;
                    float2 s = *(const float2*)&aux[(size_t)(r0+8)*ldc + cc];
                    v1.x += s.x; v1.y += s.y;
                } else if (MODE==2 || MODE==3){
                    float2 b = *(const float2*)&aux[cc];
                    v0.x += b.x; v0.y += b.y;
                    v1.x += b.x; v1.y += b.y;
                    if (MODE==3){
                        v0.x = softplus_f(v0.x); v0.y = softplus_f(v0.y);
                        v1.x = softplus_f(v1.x); v1.y = softplus_f(v1.y);
                    }
                }
                *(float2*)&C[(size_t)r0*ldc + cc]     = v0;
                *(float2*)&C[(size_t)(r0+8)*ldc + cc] = v1;
                if (SPLIT){
                    __half h0,l0,h1,l1;
                    split_f(v0.x, h0, l0); split_f(v0.y, h1, l1);
                    *(__half2*)&Ch[(size_t)r0*ldc + cc] = __halves2half2(h0,h1);
                    *(__half2*)&Cl[(size_t)r0*ldc + cc] = __halves2half2(l0,l1);
                    split_f(v1.x, h0, l0); split_f(v1.y, h1, l1);
                    *(__half2*)&Ch[(size_t)(r0+8)*ldc + cc] = __halves2half2(h0,h1);
                    *(__half2*)&Cl[(size_t)(r0+8)*ldc + cc] = __halves2half2(l0,l1);
                }
            }
        }
    }
}

// ---------------- split-K reduce (x_proj only) -------------------------------
__global__ void reduce4_split(const float* __restrict__ P,
                              float* __restrict__ proj,
                              __half* __restrict__ ph, __half* __restrict__ pl)
{
    int i = blockIdx.x*blockDim.x + threadIdx.x;
    if (i >= MROWS*PROJW) return;
    const int N = MROWS*PROJW;
    float s = (P[i] + P[N + i]) + (P[2*N + i] + P[3*N + i]);
    proj[i] = s;
    __half h, l; split_f(s, h, l);
    ph[i] = h; pl[i] = l;
}

// ------- fused LN kernels: consume 3 split-K partials, produce t & splits ---
// MODE_T 0: t_new = P0 + P1 + P2 + bias[c]   (patch output)
//        1: t_new = t + P0 + P1 + P2         (residual accumulate)
template<int MODE_T>
__global__ void ln_split_fused(const float* __restrict__ P,
                               const float* __restrict__ bias,
                               float* __restrict__ tbuf,
                               const float* __restrict__ w,
                               const float* __restrict__ b,
                               __half* __restrict__ oh, __half* __restrict__ ol)
{
    int row  = blockIdx.x*8 + (threadIdx.x >> 5);
    int lane = threadIdx.x & 31;
    const size_t rb = (size_t)row*DMODEL;
    const size_t NP = (size_t)MROWS*DMODEL;
    float v[12]; float s=0.f, sq=0.f;
    #pragma unroll
    for (int i=0;i<12;i++){
        int c = lane + i*32;
        float tn = (P[rb + c] + P[NP + rb + c]) + P[2*NP + rb + c];
        if (MODE_T == 0) tn += bias[c];
        else             tn += tbuf[rb + c];
        tbuf[rb + c] = tn;
        v[i] = tn; s += tn; sq += tn*tn;
    }
    #pragma unroll
    for (int o=16;o;o>>=1){
        s  += __shfl_xor_sync(0xffffffffu, s,  o);
        sq += __shfl_xor_sync(0xffffffffu, sq, o);
    }
    float m   = s  * (1.f/DMODEL);
    float var = sq * (1.f/DMODEL) - m*m;
    float r   = rsqrtf(var + 1e-5f);
    #pragma unroll
    for (int i=0;i<12;i++){
        int c = lane + i*32;
        float o = (v[i]-m)*r*w[c] + b[c];
        __half h, l; split_f(o, h, l);
        oh[rb + c] = h;
        ol[rb + c] = l;
    }
}

// final LN fused with residual reduce: xn = LN(t + P0 + P1 + P2)
__global__ void layernorm_fused(const float* __restrict__ P,
                                const float* __restrict__ tbuf,
                                const float* __restrict__ w,
                                const float* __restrict__ b,
                                float* __restrict__ out)
{
    int row  = blockIdx.x*8 + (threadIdx.x >> 5);
    int lane = threadIdx.x & 31;
    const size_t rb = (size_t)row*DMODEL;
    const size_t NP = (size_t)MROWS*DMODEL;
    float v[12]; float s=0.f, sq=0.f;
    #pragma unroll
    for (int i=0;i<12;i++){
        int c = lane + i*32;
        float tn = tbuf[rb + c] + (P[rb + c] + P[NP + rb + c]) + P[2*NP + rb + c];
        v[i] = tn; s += tn; sq += tn*tn;
    }
    #pragma unroll
    for (int o=16;o;o>>=1){
        s  += __shfl_xor_sync(0xffffffffu, s,  o);
        sq += __shfl_xor_sync(0xffffffffu, sq, o);
    }
    float m   = s  * (1.f/DMODEL);
    float var = sq * (1.f/DMODEL) - m*m;
    float r   = rsqrtf(var + 1e-5f);
    #pragma unroll
    for (int i=0;i<12;i++){
        int c = lane + i*32;
        out[rb + c] = (v[i]-m)*r*w[c] + b[c];
    }
}

// ---------------- causal depthwise conv1d + bias + silu, split out ---------
__global__ void conv_silu_k(const float* __restrict__ xz,
                            const float* __restrict__ cw,
                            const float* __restrict__ cb,
                            float* __restrict__ xb,
                            __half* __restrict__ xbh, __half* __restrict__ xbl)
{
    int idx = blockIdx.x*blockDim.x + threadIdx.x;
    if (idx >= MROWS*DIN) return;
    int d  = idx % DIN;
    int bl_ = idx / DIN;
    int l  = bl_ & 255;
    int b  = bl_ >> 8;
    float acc = cb[d];
    #pragma unroll
    for (int j=0;j<4;j++){
        int ls = l - 3 + j;
        if (ls >= 0)
            acc = fmaf(xz[(size_t)(b*LSEQ+ls)*(2*DIN) + d], cw[d*4+j], acc);
    }
    float o = silu_f(acc);
    xb[idx] = o;
    __half h, lo; split_f(o, h, lo);
    xbh[idx] = h; xbl[idx] = lo;
}

// ---------------- selective scan: thread per (b,d, n-quad) ------------------
__global__ void __launch_bounds__(256) scan_k(
                       const float* __restrict__ dtp,
                       const float* __restrict__ xbp,
                       const float* __restrict__ proj,
                       const float* __restrict__ xz,
                       const float* __restrict__ A_log,
                       const float* __restrict__ Dp,
                       __half* __restrict__ yh, __half* __restrict__ yl)
{
    const int tid = threadIdx.x;
    const int nq  = tid & 3;
    const int dl  = tid >> 2;
    const int d   = blockIdx.x*64 + dl;
    const int b   = blockIdx.y;

    float A[4];
    bool okf = true;
    #pragma unroll
    for (int j=0;j<4;j++){
        int n = nq*4 + j;
        A[j] = -__expf(A_log[d*NST + n]);
        float kf = (float)(n+1);
        okf = okf && (fabsf(-A[j] - kf) <= 1e-5f*kf);
    }
    const bool fast = __all_sync(0xffffffffu, okf);
    const float Dd = Dp[d];
    float h0=0.f, h1=0.f, h2=0.f, h3=0.f;
    const size_t base = (size_t)b*LSEQ;

    size_t row = base;
    float dt_c = dtp[row*DIN + d];
    float xv_c = xbp[row*DIN + d];
    float4 B_c = *(const float4*)&proj[row*PROJW + RLOW + nq*4];
    float4 C_c = *(const float4*)&proj[row*PROJW + RLOW + NST + nq*4];

    for (int l=0; l<LSEQ; l++){
        row = base + l;
        float dt = dt_c, xv = xv_c;
        float4 Bv = B_c, Cv = C_c;
        if (l+1 < LSEQ){
            size_t r2 = row + 1;
            dt_c = dtp[r2*DIN + d];
            xv_c = xbp[r2*DIN + d];
            B_c  = *(const float4*)&proj[r2*PROJW + RLOW + nq*4];
            C_c  = *(const float4*)&proj[r2*PROJW + RLOW + NST + nq*4];
        }
        float dtx = dt*xv;
        if (fast){
            float e1 = __expf(-dt);
            float e2 = e1*e1;
            float e4 = e2*e2;
            float e8 = e4*e4;
            float bp = 1.f;
            if (nq & 1) bp = e4;
            if (nq & 2) bp *= e8;
            float r = bp*e1;
            h0 = fmaf(h0, r, dtx*Bv.x); r *= e1;
            h1 = fmaf(h1, r, dtx*Bv.y); r *= e1;
            h2 = fmaf(h2, r, dtx*Bv.z); r *= e1;
            h3 = fmaf(h3, r, dtx*Bv.w);
        } else {
            h0 = fmaf(h0, __expf(dt*A[0]), dtx*Bv.x);
            h1 = fmaf(h1, __expf(dt*A[1]), dtx*Bv.y);
            h2 = fmaf(h2, __expf(dt*A[2]), dtx*Bv.z);
            h3 = fmaf(h3, __expf(dt*A[3]), dtx*Bv.w);
        }
        float p = h0*Cv.x + h1*Cv.y + h2*Cv.z + h3*Cv.w;
        p += __shfl_xor_sync(0xffffffffu, p, 1);
        p += __shfl_xor_sync(0xffffffffu, p, 2);
        if (nq == 0){
            float z = xz[row*(2*DIN) + DIN + d];
            float yv = (p + xv*Dd) * silu_f(z);
            __half hh, ll; split_f(yv, hh, ll);
            yh[row*DIN + d] = hh;
            yl[row*DIN + d] = ll;
        }
    }
}

// ---------------- mean-pool over L ------------------------------------------
__global__ void pool_k(const float* __restrict__ ln, float* __restrict__ out)
{
    int b = blockIdx.x;
    int d = threadIdx.x;
    float s = 0.f;
    for (int l=0;l<LSEQ;l++)
        s += ln[(size_t)(b*LSEQ+l)*DMODEL + d];
    out[b*DMODEL + d] = s * (1.f/LSEQ);
}

// ---------------- classifier head -------------------------------------------
__global__ void classifier_k(const float* __restrict__ pool,
                             const float* __restrict__ w,
                             const float* __restrict__ bias,
                             float* __restrict__ out)
{
    int idx = blockIdx.x*blockDim.x + threadIdx.x;
    if (idx >= NCLS*BATCH) return;
    int b = idx & 31;
    int n = idx >> 5;
    const float* pr = pool + b*DMODEL;
    const float* wr = w + (size_t)n*DMODEL;
    float acc = bias[n];
    #pragma unroll 4
    for (int k=0;k<DMODEL;k++)
        acc = fmaf(pr[k], wr[k], acc);
    out[b*NCLS + n] = acc;
}

// ---------------- launch -----------------------------------------------------
extern "C" void kernel_launch(void* const* d_in, const int* in_sizes, int n_in,
                              void* d_out, int out_size)
{
    const float* x         = (const float*)d_in[0];
    const float* patch_w   = (const float*)d_in[1];
    const float* patch_b   = (const float*)d_in[2];
    const float* norm_w    = (const float*)d_in[3];
    const float* norm_b    = (const float*)d_in[4];
    const float* in_proj_w = (const float*)d_in[5];
    const float* conv_w    = (const float*)d_in[6];
    const float* conv_b    = (const float*)d_in[7];
    const float* A_log     = (const float*)d_in[8];
    const float* D_ssm     = (const float*)d_in[9];
    const float* xproj_w   = (const float*)d_in[10];
    const float* dtproj_w  = (const float*)d_in[11];
    const float* dtproj_b  = (const float*)d_in[12];
    const float* out_proj_w= (const float*)d_in[13];
    const float* fnorm_w   = (const float*)d_in[14];
    const float* fnorm_b   = (const float*)d_in[15];
    const float* cls_w     = (const float*)d_in[16];
    const float* cls_b     = (const float*)d_in[17];
    float* out = (float*)d_out;

    float *t, *xn, *xz, *xb, *proj, *dt, *pool, *part;
    __half *wh, *wl, *imh, *iml, *xnh, *xnl, *xbh, *xbl, *prh, *prl, *yh, *yl;
    cudaGetSymbolAddress((void**)&t,    g_t);
    cudaGetSymbolAddress((void**)&xn,   g_xn);
    cudaGetSymbolAddress((void**)&xz,   g_xz);
    cudaGetSymbolAddress((void**)&xb,   g_xb);
    cudaGetSymbolAddress((void**)&proj, g_proj);
    cudaGetSymbolAddress((void**)&dt,   g_dt);
    cudaGetSymbolAddress((void**)&pool, g_pool);
    cudaGetSymbolAddress((void**)&part, g_part);
    cudaGetSymbolAddress((void**)&wh,   g_wh);
    cudaGetSymbolAddress((void**)&wl,   g_wl);
    cudaGetSymbolAddress((void**)&imh,  g_imh);
    cudaGetSymbolAddress((void**)&iml,  g_iml);
    cudaGetSymbolAddress((void**)&xnh,  g_xnh);
    cudaGetSymbolAddress((void**)&xnl,  g_xnl);
    cudaGetSymbolAddress((void**)&xbh,  g_xbh);
    cudaGetSymbolAddress((void**)&xbl,  g_xbl);
    cudaGetSymbolAddress((void**)&prh,  g_prh);
    cudaGetSymbolAddress((void**)&prl,  g_prl);
    cudaGetSymbolAddress((void**)&yh,   g_yh);
    cudaGetSymbolAddress((void**)&yl,   g_yl);

    cudaFuncSetAttribute((const void*)mma_gemm<0,0,2>, cudaFuncAttributeMaxDynamicSharedMemorySize, SMEM_G);
    cudaFuncSetAttribute((const void*)mma_gemm<3,0,2>, cudaFuncAttributeMaxDynamicSharedMemorySize, SMEM_G);
    cudaFuncSetAttribute((const void*)mma_gemm<4,0,2>, cudaFuncAttributeMaxDynamicSharedMemorySize, SMEM_G);
    cudaFuncSetAttribute((const void*)mma_gemm<4,0,3>, cudaFuncAttributeMaxDynamicSharedMemorySize, SMEM_G);

    split_weights<<<(TOTW + 255)/256, 256>>>(patch_w, in_proj_w, xproj_w,
                                             dtproj_w, out_proj_w, wh, wl);
    im2col_split<<<(MROWS*KPAD + 255)/256, 256>>>(x, imh, iml);

    // patch embed: split-K x3 (NC=19 -> 7+7+5) -> partials (reduce in LN l=0)
    mma_gemm<4,0,2><<<dim3(3,64,3), 256, SMEM_G>>>(imh, iml, KPAD,
        wh, wl, DMODEL, part, DMODEL, KPAD, nullptr, nullptr, nullptr, 7);

    for (int l=0; l<NLAYER; l++){
        // fused: t = (l==0 ? P0+P1+P2+patch_b : t + P0+P1+P2); LN; split
        if (l == 0)
            ln_split_fused<0><<<1024, 256>>>(part, patch_b, t,
                norm_w, norm_b, xnh, xnl);
        else
            ln_split_fused<1><<<1024, 256>>>(part, nullptr, t,
                norm_w + l*DMODEL, norm_b + l*DMODEL, xnh, xnl);
        // in_proj: 768 CTAs, well balanced -> direct
        mma_gemm<0,0,2><<<dim3(12,64), 256, SMEM_G>>>(xnh, xnl, DMODEL,
            wh + OFF_IN + (size_t)l*SZ_IN, wl + OFF_IN + (size_t)l*SZ_IN, 2*DIN,
            xz, 2*DIN, DMODEL, nullptr, nullptr, nullptr, 0);
        conv_silu_k<<<(MROWS*DIN + 255)/256, 256>>>(xz,
            conv_w + (size_t)l*DIN*4, conv_b + l*DIN, xb, xbh, xbl);
        // x_proj: split-K x4, reduce + split out
        mma_gemm<4,0,2><<<dim3(1,64,4), 256, SMEM_G>>>(xbh, xbl, DIN,
            wh + OFF_XP + (size_t)l*SZ_XP, wl + OFF_XP + (size_t)l*SZ_XP, PROJW,
            part, PROJW, DIN, nullptr, nullptr, nullptr, 6);
        reduce4_split<<<(MROWS*PROJW + 255)/256, 256>>>(part, proj, prh, prl);
        // dt_proj + softplus -> direct
        mma_gemm<3,0,2><<<dim3(6,64), 256, SMEM_G>>>(prh, prl, PROJW,
            wh + OFF_DT + (size_t)l*SZ_DT, wl + OFF_DT + (size_t)l*SZ_DT, DIN,
            dt, DIN, RLOW, dtproj_b + l*DIN, nullptr, nullptr, 0);
        // selective scan
        scan_k<<<dim3(12,32), 256>>>(dt, xb, proj, xz,
            A_log + (size_t)l*DIN*NST, D_ssm + l*DIN, yh, yl);
        // out_proj: split-K x3 (NC=24 -> 8 each, NPROD3) -> partials
        mma_gemm<4,0,3><<<dim3(3,64,3), 256, SMEM_G>>>(yh, yl, DIN,
            wh + OFF_OW + (size_t)l*SZ_OW, wl + OFF_OW + (size_t)l*SZ_OW, DMODEL,
            part, DMODEL, DIN, nullptr, nullptr, nullptr, 8);
    }

    // final LN fused with last residual reduce
    layernorm_fused<<<1024, 256>>>(part, t, fnorm_w, fnorm_b, xn);
    pool_k<<<BATCH, DMODEL>>>(xn, pool);
    classifier_k<<<(NCLS*BATCH + 255)/256, 256>>>(pool, cls_w, cls_b, out);
}